// round 12
// baseline (speedup 1.0000x reference)
#include <cuda_runtime.h>
#include <cstdint>

// Problem constants
#define DM   1024
#define NH   16
#define HD   64
#define BB   2
#define TT   2048

// k-interleave within groups of 8: pos(k) = (k&3)*2 + (k>>2)
// inverse: old(p) = (p>>1) + (p&1)*4

// Scratch (device globals: allocation-free rule)
__device__ float g_qkv[3 * BB * NH * TT * HD];   // Q,K d-interleaved; V plain
__device__ float g_att[BB * TT * DM];            // d-interleaved (proj A operand)
__device__ float g_xr[BB * TT * DM];             // x, tf32-rounded, k-interleaved
__device__ float g_wqr[DM * 3 * DM];             // w_qkv, tf32-rounded, plain
__device__ float g_wpr[DM * DM];                 // w_proj, tf32-rounded, plain

// ---------------------------------------------------------------------------
// helpers
// ---------------------------------------------------------------------------
__device__ __forceinline__ float to_tf32(float x) {
    uint32_t u;
    asm("cvt.rna.tf32.f32 %0, %1;" : "=r"(u) : "f"(x));
    return __uint_as_float(u);
}
__device__ __forceinline__ float ex2(float x) {
    float r;
    asm("ex2.approx.f32 %0, %1;" : "=f"(r) : "f"(x));
    return r;
}

__device__ __forceinline__ void mma_tf32(float& c0, float& c1, float& c2, float& c3,
                                         uint32_t a0, uint32_t a1, uint32_t a2, uint32_t a3,
                                         uint32_t b0, uint32_t b1) {
    asm volatile(
        "mma.sync.aligned.m16n8k8.row.col.f32.tf32.tf32.f32 "
        "{%0,%1,%2,%3}, {%4,%5,%6,%7}, {%8,%9}, {%0,%1,%2,%3};"
        : "+f"(c0), "+f"(c1), "+f"(c2), "+f"(c3)
        : "r"(a0), "r"(a1), "r"(a2), "r"(a3), "r"(b0), "r"(b1));
}

__device__ __forceinline__ uint32_t smem_u32(const void* p) {
    uint32_t a;
    asm("{ .reg .u64 t; cvta.to.shared.u64 t, %1; cvt.u32.u64 %0, t; }"
        : "=r"(a) : "l"(p));
    return a;
}
__device__ __forceinline__ void cpa16(uint32_t saddr, const void* g) {
    asm volatile("cp.async.cg.shared.global [%0], [%1], 16;"
                 :: "r"(saddr), "l"(g) : "memory");
}
#define CP_COMMIT() asm volatile("cp.async.commit_group;" ::: "memory")
#define CP_WAIT1()  asm volatile("cp.async.wait_group 1;" ::: "memory")
#define CP_WAIT0()  asm volatile("cp.async.wait_group 0;" ::: "memory")

// ---------------------------------------------------------------------------
// Merged prepass: tf32-round; x additionally k-interleaved (8-groups).
// x processed in 8-float units: out[p0..3]=(in0,in4,in1,in5), out[p4..7]=(in2,in6,in3,in7)
// ---------------------------------------------------------------------------
#define N8_X  (BB * TT * DM / 8)
#define N4_WQ (DM * 3 * DM / 4)
#define N4_WP (DM * DM / 4)

__global__ __launch_bounds__(256) void round_all(const float* __restrict__ x,
                                                 const float* __restrict__ wq,
                                                 const float* __restrict__ wp)
{
    const int total = N8_X + N4_WQ + N4_WP;
    const int stride = gridDim.x * blockDim.x;
    for (int i = blockIdx.x * blockDim.x + threadIdx.x; i < total; i += stride) {
        int j = i;
        if (j < N8_X) {
            float4 lo = *(const float4*)(x + (size_t)j * 8);
            float4 hi = *(const float4*)(x + (size_t)j * 8 + 4);
            float4 oA = { to_tf32(lo.x), to_tf32(hi.x), to_tf32(lo.y), to_tf32(hi.y) };
            float4 oB = { to_tf32(lo.z), to_tf32(hi.z), to_tf32(lo.w), to_tf32(hi.w) };
            *(float4*)((float*)g_xr + (size_t)j * 8)     = oA;
            *(float4*)((float*)g_xr + (size_t)j * 8 + 4) = oB;
        } else {
            const float* src;
            float* dst;
            if ((j -= N8_X) < N4_WQ) { src = wq; dst = (float*)g_wqr; }
            else { j -= N4_WQ; src = wp; dst = (float*)g_wpr; }
            float4 v = *(const float4*)(src + (size_t)j * 4);
            v.x = to_tf32(v.x); v.y = to_tf32(v.y);
            v.z = to_tf32(v.z); v.w = to_tf32(v.w);
            *(float4*)(dst + (size_t)j * 4) = v;
        }
    }
}

// ---------------------------------------------------------------------------
// tf32 GEMM, BK=32, 3-stage cp.async.  A is k-interleaved -> LDS.64 frags.
// A stage [128][40] (stride 8 mod 32: conflict-free LDS.64),
// B stage [32][132] (stride 4 mod 32: conflict-free scalar).
// MODE 0: A=g_xr; epilogue: which<2 written d-interleaved, V plain.
// MODE 1: A=g_att (interleaved); epilogue plain C.
// ---------------------------------------------------------------------------
#define AS_STRIDE (128 * 40)
#define BS_STRIDE (32 * 132)
#define GSMEM_BYTES ((3 * AS_STRIDE + 3 * BS_STRIDE) * 4)

template <int MODE>
__global__ __launch_bounds__(256) void mma_gemm(const float* __restrict__ bias,
                                                float* __restrict__ C,
                                                int M, int N, int K)
{
    extern __shared__ float dsm[];
    float* AsF = dsm;
    float* BsF = dsm + 3 * AS_STRIDE;
    const uint32_t abase = smem_u32(AsF);
    const uint32_t bbase = smem_u32(BsF);

    const int tid  = threadIdx.x;
    const int bm   = blockIdx.y * 128;
    const int bn   = blockIdx.x * 128;
    const int w    = tid >> 5;
    const int lane = tid & 31;
    const int g    = lane >> 2;
    const int t    = lane & 3;
    const int m0   = (w & 3) * 32;
    const int n0   = (w >> 2) * 64;

    const float* Aeff = (MODE == 0) ? (const float*)g_xr : (const float*)g_att;
    const float* Bw   = (MODE == 0) ? (const float*)g_wqr : (const float*)g_wpr;

    float acc[2][8][4];
#pragma unroll
    for (int mt = 0; mt < 2; mt++)
#pragma unroll
        for (int nt = 0; nt < 8; nt++)
#pragma unroll
            for (int r = 0; r < 4; r++) acc[mt][nt][r] = 0.f;

    int arow[4], ac4[4], brow[4], bc4[4];
#pragma unroll
    for (int j = 0; j < 4; j++) {
        const int f = tid + 256 * j;
        arow[j] = f >> 3;  ac4[j] = (f & 7) * 4;
        brow[j] = f >> 5;  bc4[j] = (f & 31) * 4;
    }

    const int NC = K >> 5;

    auto issue = [&](int c) {
        const int s = c % 3;
        const uint32_t as = abase + (uint32_t)(s * AS_STRIDE) * 4u;
        const uint32_t bs = bbase + (uint32_t)(s * BS_STRIDE) * 4u;
        const int k0 = c << 5;
#pragma unroll
        for (int j = 0; j < 4; j++) {
            cpa16(as + (uint32_t)(arow[j] * 40 + ac4[j]) * 4u,
                  Aeff + (size_t)(bm + arow[j]) * K + k0 + ac4[j]);
            cpa16(bs + (uint32_t)(brow[j] * 132 + bc4[j]) * 4u,
                  Bw + (size_t)(k0 + brow[j]) * N + bn + bc4[j]);
        }
    };

    issue(0); CP_COMMIT();
    issue(1); CP_COMMIT();

    for (int c = 0; c < NC; c++) {
        const int st = c % 3;
        CP_WAIT1();
        __syncthreads();

        if (c + 2 < NC) issue(c + 2);
        CP_COMMIT();

        const float* As = AsF + st * AS_STRIDE;
        const float* Bs = BsF + st * BS_STRIDE;
#pragma unroll
        for (int ks = 0; ks < 4; ks++) {
            const int kb = ks * 8;
            uint32_t af[2][4], bf[8][2];
#pragma unroll
            for (int mt = 0; mt < 2; mt++) {
                const int m = m0 + mt * 16 + g;
                // interleaved: pos kb+2t holds k=kb+t, pos kb+2t+1 holds k=kb+t+4
                float2 a0 = *(const float2*)&As[m * 40 + kb + 2 * t];
                float2 a1 = *(const float2*)&As[(m + 8) * 40 + kb + 2 * t];
                af[mt][0] = __float_as_uint(a0.x);
                af[mt][1] = __float_as_uint(a1.x);
                af[mt][2] = __float_as_uint(a0.y);
                af[mt][3] = __float_as_uint(a1.y);
            }
#pragma unroll
            for (int nt = 0; nt < 8; nt++) {
                const int n = n0 + nt * 8 + g;
                bf[nt][0] = __float_as_uint(Bs[(kb + t) * 132 + n]);
                bf[nt][1] = __float_as_uint(Bs[(kb + t + 4) * 132 + n]);
            }
#pragma unroll
            for (int mt = 0; mt < 2; mt++)
#pragma unroll
                for (int nt = 0; nt < 8; nt++)
                    mma_tf32(acc[mt][nt][0], acc[mt][nt][1],
                             acc[mt][nt][2], acc[mt][nt][3],
                             af[mt][0], af[mt][1], af[mt][2], af[mt][3],
                             bf[nt][0], bf[nt][1]);
        }
    }

    const int ng = bn + n0;
    if (MODE == 0) {
        const int which = ng >> 10;
        const int rem   = ng & 1023;
        const int h     = rem >> 6;
        // p0 = newpos(2t), pairs (p0, p0+2)
        const int p0 = ((2 * t) & 3) * 2 + ((2 * t) >> 2);
#pragma unroll
        for (int mt = 0; mt < 2; mt++) {
            const int row0 = bm + m0 + mt * 16 + g;
            const int row1 = row0 + 8;
            const int b0i = row0 >> 11, t0i = row0 & 2047;
            const int b1i = row1 >> 11, t1i = row1 & 2047;
            float* base0 = g_qkv + ((size_t)((which * BB + b0i) * NH + h) * TT + t0i) * HD;
            float* base1 = g_qkv + ((size_t)((which * BB + b1i) * NH + h) * TT + t1i) * HD;
#pragma unroll
            for (int nt = 0; nt < 8; nt++) {
                const int d = nt * 8 + 2 * t;
                const float bx = bias[ng + d], by = bias[ng + d + 1];
                const float v00 = to_tf32(acc[mt][nt][0] + bx);
                const float v01 = to_tf32(acc[mt][nt][1] + by);
                const float v10 = to_tf32(acc[mt][nt][2] + bx);
                const float v11 = to_tf32(acc[mt][nt][3] + by);
                if (which < 2) {   // Q,K: d-interleaved
                    base0[nt * 8 + p0]     = v00;
                    base0[nt * 8 + p0 + 2] = v01;
                    base1[nt * 8 + p0]     = v10;
                    base1[nt * 8 + p0 + 2] = v11;
                } else {           // V: plain
                    *(float2*)(base0 + d) = make_float2(v00, v01);
                    *(float2*)(base1 + d) = make_float2(v10, v11);
                }
            }
        }
    } else {
#pragma unroll
        for (int mt = 0; mt < 2; mt++) {
            const int row0 = bm + m0 + mt * 16 + g;
            const int row1 = row0 + 8;
#pragma unroll
            for (int nt = 0; nt < 8; nt++) {
                const int n = ng + nt * 8 + 2 * t;
                const float bx = bias[n], by = bias[n + 1];
                float2 o0 = { acc[mt][nt][0] + bx, acc[mt][nt][1] + by };
                float2 o1 = { acc[mt][nt][2] + bx, acc[mt][nt][3] + by };
                *(float2*)(C + (size_t)row0 * N + n) = o0;
                *(float2*)(C + (size_t)row1 * N + n) = o1;
            }
        }
    }
}

// ---------------------------------------------------------------------------
// Flash attention, tf32 mma.sync, 2-stage cp.async K/V, exp2 softmax,
// warp causal skip.  Q,K d-interleaved -> LDS.64 frags (K stride 72,
// 8 mod 32: conflict-free).  V plain (stride 72).  P plain (stride 68).
// ---------------------------------------------------------------------------
#define FK_TILE  (64 * 72)
#define FV_TILE  (64 * 72)
#define FLASH_SMEM ((2 * FK_TILE + 2 * FV_TILE + 128 * 68) * 4)

__global__ __launch_bounds__(256, 2) void flash_mma()
{
    extern __shared__ float sm[];
    float* Vb = sm + 2 * FK_TILE;
    float* Ps = sm + 2 * FK_TILE + 2 * FV_TILE;    // [128][68]: Q staging, then P
    const uint32_t smb = smem_u32(sm);
    const uint32_t vmb = smem_u32(Vb);

    const int tid  = threadIdx.x;
    const int w    = tid >> 5;
    const int lane = tid & 31;
    const int g    = lane >> 2;
    const int t    = lane & 3;
    const int qt   = (int)gridDim.x - 1 - (int)blockIdx.x;  // heavy CTAs first
    const int h    = blockIdx.y;
    const int b    = blockIdx.z;
    const int q_base = qt * 128;
    const int mb     = w * 16;

    const float* Qg = g_qkv + ((size_t)((0 * BB + b) * NH + h) * TT) * HD;
    const float* Kg = g_qkv + ((size_t)((1 * BB + b) * NH + h) * TT) * HD;
    const float* Vg = g_qkv + ((size_t)((2 * BB + b) * NH + h) * TT) * HD;

    int frow[4], fc4[4];
#pragma unroll
    for (int j = 0; j < 4; j++) {
        const int v = tid + 256 * j;
        frow[j] = v >> 4;
        fc4[j]  = (v & 15) * 4;
    }

    auto issue_kv = [&](int kt) {
        const int s = kt & 1;
        const uint32_t kb = smb + (uint32_t)(s * FK_TILE) * 4u;
        const uint32_t vb = vmb + (uint32_t)(s * FV_TILE) * 4u;
        const float* Kt = Kg + (size_t)(kt * 64) * HD;
        const float* Vt = Vg + (size_t)(kt * 64) * HD;
#pragma unroll
        for (int j = 0; j < 4; j++) {
            const size_t go = (size_t)frow[j] * HD + fc4[j];
            cpa16(kb + (uint32_t)(frow[j] * 72 + fc4[j]) * 4u, Kt + go);
            cpa16(vb + (uint32_t)(frow[j] * 72 + fc4[j]) * 4u, Vt + go);
        }
    };

    issue_kv(0); CP_COMMIT();

    // stage Q (already tf32 + d-interleaved); prescale by 0.125*log2(e)
    const float QS = 0.18033688011112042f;
    for (int i = tid; i < 2048; i += 256) {
        const int row = i >> 4, c4 = (i & 15) * 4;
        float4 v = *(const float4*)(Qg + (size_t)(q_base + row) * HD + c4);
        v.x = to_tf32(v.x * QS); v.y = to_tf32(v.y * QS);
        v.z = to_tf32(v.z * QS); v.w = to_tf32(v.w * QS);
        *(float4*)&Ps[row * 68 + c4] = v;
    }
    __syncthreads();

    uint32_t qa[8][4];
#pragma unroll
    for (int ks = 0; ks < 8; ks++) {
        const int kb = ks * 8;
        float2 q0 = *(const float2*)&Ps[(mb + g) * 68 + kb + 2 * t];
        float2 q1 = *(const float2*)&Ps[(mb + g + 8) * 68 + kb + 2 * t];
        qa[ks][0] = __float_as_uint(q0.x);
        qa[ks][1] = __float_as_uint(q1.x);
        qa[ks][2] = __float_as_uint(q0.y);
        qa[ks][3] = __float_as_uint(q1.y);
    }

    float oacc[8][4];
#pragma unroll
    for (int nt = 0; nt < 8; nt++)
#pragma unroll
        for (int r = 0; r < 4; r++) oacc[nt][r] = 0.f;
    float m0 = -1e30f, m1 = -1e30f, l0 = 0.f, l1 = 0.f;
    const int r0 = q_base + mb + g, r1 = r0 + 8;

    const int nkt = 2 * qt + 2;
    for (int kt = 0; kt < nkt; kt++) {
        const int st = kt & 1;
        float* Ks = sm + st * FK_TILE;
        float* Vs = Vb + st * FV_TILE;

        CP_WAIT0();
        __syncthreads();

        if (kt + 1 < nkt) issue_kv(kt + 1);
        CP_COMMIT();

        if (kt * 64 > q_base + mb + 15) continue;   // fully-masked: bit-exact skip

        // S = Q @ K^T
        float sacc[8][4];
#pragma unroll
        for (int nt = 0; nt < 8; nt++)
#pragma unroll
            for (int r = 0; r < 4; r++) sacc[nt][r] = 0.f;
#pragma unroll
        for (int ks = 0; ks < 8; ks++) {
            const int kb = ks * 8;
            uint32_t bf[8][2];
#pragma unroll
            for (int nt = 0; nt < 8; nt++) {
                float2 k2 = *(const float2*)&Ks[(nt * 8 + g) * 72 + kb + 2 * t];
                bf[nt][0] = __float_as_uint(k2.x);
                bf[nt][1] = __float_as_uint(k2.y);
            }
#pragma unroll
            for (int nt = 0; nt < 8; nt++)
                mma_tf32(sacc[nt][0], sacc[nt][1], sacc[nt][2], sacc[nt][3],
                         qa[ks][0], qa[ks][1], qa[ks][2], qa[ks][3],
                         bf[nt][0], bf[nt][1]);
        }

        if (kt >= 2 * qt) {
            const int sb = kt * 64;
#pragma unroll
            for (int nt = 0; nt < 8; nt++) {
                const int c0 = sb + nt * 8 + 2 * t, c1 = c0 + 1;
                if (c0 > r0) sacc[nt][0] = -1e30f;
                if (c1 > r0) sacc[nt][1] = -1e30f;
                if (c0 > r1) sacc[nt][2] = -1e30f;
                if (c1 > r1) sacc[nt][3] = -1e30f;
            }
        }

        float mx0 = -1e30f, mx1 = -1e30f;
#pragma unroll
        for (int nt = 0; nt < 8; nt++) {
            mx0 = fmaxf(mx0, fmaxf(sacc[nt][0], sacc[nt][1]));
            mx1 = fmaxf(mx1, fmaxf(sacc[nt][2], sacc[nt][3]));
        }
        mx0 = fmaxf(mx0, __shfl_xor_sync(0xffffffffu, mx0, 1));
        mx0 = fmaxf(mx0, __shfl_xor_sync(0xffffffffu, mx0, 2));
        mx1 = fmaxf(mx1, __shfl_xor_sync(0xffffffffu, mx1, 1));
        mx1 = fmaxf(mx1, __shfl_xor_sync(0xffffffffu, mx1, 2));

        const float mn0 = fmaxf(m0, mx0), mn1 = fmaxf(m1, mx1);
        const float f0 = ex2(m0 - mn0), f1 = ex2(m1 - mn1);
        float ls0 = 0.f, ls1 = 0.f;
#pragma unroll
        for (int nt = 0; nt < 8; nt++) {
            const float p00 = ex2(sacc[nt][0] - mn0);
            const float p01 = ex2(sacc[nt][1] - mn0);
            const float p10 = ex2(sacc[nt][2] - mn1);
            const float p11 = ex2(sacc[nt][3] - mn1);
            ls0 += p00 + p01;
            ls1 += p10 + p11;
            float2 s0 = { to_tf32(p00), to_tf32(p01) };
            float2 s1 = { to_tf32(p10), to_tf32(p11) };
            *(float2*)&Ps[(mb + g) * 68 + nt * 8 + 2 * t]     = s0;
            *(float2*)&Ps[(mb + g + 8) * 68 + nt * 8 + 2 * t] = s1;
        }
        ls0 += __shfl_xor_sync(0xffffffffu, ls0, 1);
        ls0 += __shfl_xor_sync(0xffffffffu, ls0, 2);
        ls1 += __shfl_xor_sync(0xffffffffu, ls1, 1);
        ls1 += __shfl_xor_sync(0xffffffffu, ls1, 2);
        l0 = l0 * f0 + ls0;
        l1 = l1 * f1 + ls1;
        m0 = mn0; m1 = mn1;
#pragma unroll
        for (int nt = 0; nt < 8; nt++) {
            oacc[nt][0] *= f0; oacc[nt][1] *= f0;
            oacc[nt][2] *= f1; oacc[nt][3] *= f1;
        }
        __syncwarp();

        // O += P @ V
#pragma unroll
        for (int ks = 0; ks < 8; ks++) {
            const int kb = ks * 8;
            uint32_t pa[4];
            pa[0] = __float_as_uint(Ps[(mb + g) * 68 + kb + t]);
            pa[1] = __float_as_uint(Ps[(mb + g + 8) * 68 + kb + t]);
            pa[2] = __float_as_uint(Ps[(mb + g) * 68 + kb + t + 4]);
            pa[3] = __float_as_uint(Ps[(mb + g + 8) * 68 + kb + t + 4]);
            uint32_t bf[8][2];
#pragma unroll
            for (int nt = 0; nt < 8; nt++) {
                bf[nt][0] = __float_as_uint(Vs[(kb + t) * 72 + nt * 8 + g]);
                bf[nt][1] = __float_as_uint(Vs[(kb + t + 4) * 72 + nt * 8 + g]);
            }
#pragma unroll
            for (int nt = 0; nt < 8; nt++)
                mma_tf32(oacc[nt][0], oacc[nt][1], oacc[nt][2], oacc[nt][3],
                         pa[0], pa[1], pa[2], pa[3], bf[nt][0], bf[nt][1]);
        }
    }

    // epilogue: tf32-round, d-interleaved (proj GEMM A operand layout)
    const float i0 = 1.0f / l0, i1 = 1.0f / l1;
    const int p0 = ((2 * t) & 3) * 2 + ((2 * t) >> 2);
    float* O0 = g_att + ((size_t)(b * TT + r0) * NH + h) * HD;
    float* O1 = g_att + ((size_t)(b * TT + r1) * NH + h) * HD;
#pragma unroll
    for (int nt = 0; nt < 8; nt++) {
        O0[nt * 8 + p0]     = to_tf32(oacc[nt][0] * i0);
        O0[nt * 8 + p0 + 2] = to_tf32(oacc[nt][1] * i0);
        O1[nt * 8 + p0]     = to_tf32(oacc[nt][2] * i1);
        O1[nt * 8 + p0 + 2] = to_tf32(oacc[nt][3] * i1);
    }
}

// ---------------------------------------------------------------------------
// kernel_launch
// ---------------------------------------------------------------------------
extern "C" void kernel_launch(void* const* d_in, const int* in_sizes, int n_in,
                              void* d_out, int out_size)
{
    const float* x      = (const float*)d_in[0];
    const float* w_qkv  = (const float*)d_in[1];
    const float* b_qkv  = (const float*)d_in[2];
    const float* w_proj = (const float*)d_in[3];
    const float* b_proj = (const float*)d_in[4];
    float* out = (float*)d_out;

    const int M = BB * TT;  // 4096

    cudaFuncSetAttribute(mma_gemm<0>, cudaFuncAttributeMaxDynamicSharedMemorySize, GSMEM_BYTES);
    cudaFuncSetAttribute(mma_gemm<1>, cudaFuncAttributeMaxDynamicSharedMemorySize, GSMEM_BYTES);
    cudaFuncSetAttribute(flash_mma, cudaFuncAttributeMaxDynamicSharedMemorySize, FLASH_SMEM);

    // 0) merged prepass: tf32-round (x also k-interleaved)
    round_all<<<1024, 256>>>(x, w_qkv, w_proj);

    // 1) QKV projection -> g_qkv (Q,K interleaved; V plain)
    mma_gemm<0><<<dim3(3 * DM / 128, M / 128), 256, GSMEM_BYTES>>>(b_qkv, nullptr, M, 3 * DM, DM);

    // 2) causal flash attention -> g_att (interleaved)
    flash_mma<<<dim3(TT / 128, NH, BB), 256, FLASH_SMEM>>>();

    // 3) output projection -> out
    mma_gemm<1><<<dim3(DM / 128, M / 128), 256, GSMEM_BYTES>>>(b_proj, out, M, DM, DM);
}

// round 13
// speedup vs baseline: 1.0720x; 1.0720x over previous
#include <cuda_runtime.h>
#include <cstdint>

// Problem constants
#define DM   1024
#define NH   16
#define HD   64
#define BB   2
#define TT   2048

// Scratch (device globals: allocation-free rule)
__device__ float g_qkv[3 * BB * NH * TT * HD];   // [which][b][h][t][d], tf32-rounded
__device__ float g_att[BB * TT * DM];            // [b][t][h][d], tf32-rounded
__device__ float g_xr[BB * TT * DM];             // x, tf32-rounded
__device__ float g_wqr[DM * 3 * DM];             // w_qkv, tf32-rounded
__device__ float g_wpr[DM * DM];                 // w_proj, tf32-rounded

// ---------------------------------------------------------------------------
// tf32 helpers (portable PTX: works on plain sm_103 target)
// ---------------------------------------------------------------------------
__device__ __forceinline__ float to_tf32(float x) {
    uint32_t u;
    asm("cvt.rna.tf32.f32 %0, %1;" : "=r"(u) : "f"(x));
    return __uint_as_float(u);
}
__device__ __forceinline__ float ex2(float x) {
    float r;
    asm("ex2.approx.f32 %0, %1;" : "=f"(r) : "f"(x));
    return r;
}

__device__ __forceinline__ void mma_tf32(float& c0, float& c1, float& c2, float& c3,
                                         uint32_t a0, uint32_t a1, uint32_t a2, uint32_t a3,
                                         uint32_t b0, uint32_t b1) {
    asm volatile(
        "mma.sync.aligned.m16n8k8.row.col.f32.tf32.tf32.f32 "
        "{%0,%1,%2,%3}, {%4,%5,%6,%7}, {%8,%9}, {%0,%1,%2,%3};"
        : "+f"(c0), "+f"(c1), "+f"(c2), "+f"(c3)
        : "r"(a0), "r"(a1), "r"(a2), "r"(a3), "r"(b0), "r"(b1));
}

__device__ __forceinline__ uint32_t smem_u32(const void* p) {
    uint32_t a;
    asm("{ .reg .u64 t; cvta.to.shared.u64 t, %1; cvt.u32.u64 %0, t; }"
        : "=r"(a) : "l"(p));
    return a;
}
__device__ __forceinline__ void cpa16(uint32_t saddr, const void* g) {
    asm volatile("cp.async.cg.shared.global [%0], [%1], 16;"
                 :: "r"(saddr), "l"(g) : "memory");
}
#define CP_COMMIT() asm volatile("cp.async.commit_group;" ::: "memory")
#define CP_WAIT1()  asm volatile("cp.async.wait_group 1;" ::: "memory")
#define CP_WAIT0()  asm volatile("cp.async.wait_group 0;" ::: "memory")

// ---------------------------------------------------------------------------
// Merged prepass: tf32-round x, w_qkv, w_proj in one launch (float4 strides)
// ---------------------------------------------------------------------------
#define N4_X  (BB * TT * DM / 4)
#define N4_WQ (DM * 3 * DM / 4)
#define N4_WP (DM * DM / 4)

__global__ __launch_bounds__(256) void round_all(const float* __restrict__ x,
                                                 const float* __restrict__ wq,
                                                 const float* __restrict__ wp)
{
    const int total = N4_X + N4_WQ + N4_WP;
    const int stride = gridDim.x * blockDim.x;
    for (int i = blockIdx.x * blockDim.x + threadIdx.x; i < total; i += stride) {
        const float* src;
        float* dst;
        int j = i;
        if (j < N4_X) { src = x; dst = (float*)g_xr; }
        else if ((j -= N4_X) < N4_WQ) { src = wq; dst = (float*)g_wqr; }
        else { j -= N4_WQ; src = wp; dst = (float*)g_wpr; }
        float4 v = *(const float4*)(src + (size_t)j * 4);
        v.x = to_tf32(v.x); v.y = to_tf32(v.y);
        v.z = to_tf32(v.z); v.w = to_tf32(v.w);
        *(float4*)(dst + (size_t)j * 4) = v;
    }
}

// ---------------------------------------------------------------------------
// tf32 tensor-core GEMM, BK=32, 3-stage cp.async pipeline, pre-rounded
// inputs.  BM=BN=128, 8 warps (32x64 each), 128 MMAs per barrier window.
// A stage [128][36] (bank = 4m+t, conflict-free), B stage [32][136]
// (bank = 8(kb+t)+n -> 8t+g distinct, conflict-free).
// ---------------------------------------------------------------------------
#define AS_STRIDE (128 * 36)
#define BS_STRIDE (32 * 136)
#define GSMEM_BYTES ((3 * AS_STRIDE + 3 * BS_STRIDE) * 4)

template <int MODE>
__global__ __launch_bounds__(256) void mma_gemm(const float* __restrict__ bias,
                                                float* __restrict__ C,
                                                int M, int N, int K)
{
    extern __shared__ float dsm[];
    float* AsF = dsm;
    float* BsF = dsm + 3 * AS_STRIDE;
    const uint32_t abase = smem_u32(AsF);
    const uint32_t bbase = smem_u32(BsF);

    const int tid  = threadIdx.x;
    const int bm   = blockIdx.y * 128;
    const int bn   = blockIdx.x * 128;
    const int w    = tid >> 5;
    const int lane = tid & 31;
    const int g    = lane >> 2;
    const int t    = lane & 3;
    const int m0   = (w & 3) * 32;
    const int n0   = (w >> 2) * 64;

    const float* Aeff = (MODE == 0) ? (const float*)g_xr : (const float*)g_att;
    const float* Bw   = (MODE == 0) ? (const float*)g_wqr : (const float*)g_wpr;

    float acc[2][8][4];
#pragma unroll
    for (int mt = 0; mt < 2; mt++)
#pragma unroll
        for (int nt = 0; nt < 8; nt++)
#pragma unroll
            for (int r = 0; r < 4; r++) acc[mt][nt][r] = 0.f;

    int arow[4], ac4[4], brow[4], bc4[4];
#pragma unroll
    for (int j = 0; j < 4; j++) {
        const int f = tid + 256 * j;
        arow[j] = f >> 3;  ac4[j] = (f & 7) * 4;
        brow[j] = f >> 5;  bc4[j] = (f & 31) * 4;
    }

    const int NC = K >> 5;

    auto issue = [&](int c) {
        const int s = c % 3;
        const uint32_t as = abase + (uint32_t)(s * AS_STRIDE) * 4u;
        const uint32_t bs = bbase + (uint32_t)(s * BS_STRIDE) * 4u;
        const int k0 = c << 5;
#pragma unroll
        for (int j = 0; j < 4; j++) {
            cpa16(as + (uint32_t)(arow[j] * 36 + ac4[j]) * 4u,
                  Aeff + (size_t)(bm + arow[j]) * K + k0 + ac4[j]);
            cpa16(bs + (uint32_t)(brow[j] * 136 + bc4[j]) * 4u,
                  Bw + (size_t)(k0 + brow[j]) * N + bn + bc4[j]);
        }
    };

    issue(0); CP_COMMIT();
    issue(1); CP_COMMIT();

    for (int c = 0; c < NC; c++) {
        const int st = c % 3;
        CP_WAIT1();
        __syncthreads();

        if (c + 2 < NC) issue(c + 2);
        CP_COMMIT();

        const float* As = AsF + st * AS_STRIDE;
        const float* Bs = BsF + st * BS_STRIDE;
#pragma unroll
        for (int ks = 0; ks < 4; ks++) {
            const int kb = ks * 8;
            uint32_t af[2][4], bf[8][2];
#pragma unroll
            for (int mt = 0; mt < 2; mt++) {
                const int m = m0 + mt * 16 + g;
                af[mt][0] = __float_as_uint(As[m * 36 + kb + t]);
                af[mt][1] = __float_as_uint(As[(m + 8) * 36 + kb + t]);
                af[mt][2] = __float_as_uint(As[m * 36 + kb + t + 4]);
                af[mt][3] = __float_as_uint(As[(m + 8) * 36 + kb + t + 4]);
            }
#pragma unroll
            for (int nt = 0; nt < 8; nt++) {
                const int n = n0 + nt * 8 + g;
                bf[nt][0] = __float_as_uint(Bs[(kb + t) * 136 + n]);
                bf[nt][1] = __float_as_uint(Bs[(kb + t + 4) * 136 + n]);
            }
#pragma unroll
            for (int mt = 0; mt < 2; mt++)
#pragma unroll
                for (int nt = 0; nt < 8; nt++)
                    mma_tf32(acc[mt][nt][0], acc[mt][nt][1],
                             acc[mt][nt][2], acc[mt][nt][3],
                             af[mt][0], af[mt][1], af[mt][2], af[mt][3],
                             bf[nt][0], bf[nt][1]);
        }
    }

    const int ng = bn + n0;
    if (MODE == 0) {
        const int which = ng >> 10;
        const int rem   = ng & 1023;
        const int h     = rem >> 6;
#pragma unroll
        for (int mt = 0; mt < 2; mt++) {
            const int row0 = bm + m0 + mt * 16 + g;
            const int row1 = row0 + 8;
            const int b0i = row0 >> 11, t0i = row0 & 2047;
            const int b1i = row1 >> 11, t1i = row1 & 2047;
            float* base0 = g_qkv + ((size_t)((which * BB + b0i) * NH + h) * TT + t0i) * HD;
            float* base1 = g_qkv + ((size_t)((which * BB + b1i) * NH + h) * TT + t1i) * HD;
#pragma unroll
            for (int nt = 0; nt < 8; nt++) {
                const int d = nt * 8 + 2 * t;
                const float bx = bias[ng + d], by = bias[ng + d + 1];
                float2 o0 = { to_tf32(acc[mt][nt][0] + bx), to_tf32(acc[mt][nt][1] + by) };
                float2 o1 = { to_tf32(acc[mt][nt][2] + bx), to_tf32(acc[mt][nt][3] + by) };
                *(float2*)(base0 + d) = o0;
                *(float2*)(base1 + d) = o1;
            }
        }
    } else {
#pragma unroll
        for (int mt = 0; mt < 2; mt++) {
            const int row0 = bm + m0 + mt * 16 + g;
            const int row1 = row0 + 8;
#pragma unroll
            for (int nt = 0; nt < 8; nt++) {
                const int n = ng + nt * 8 + 2 * t;
                const float bx = bias[n], by = bias[n + 1];
                float2 o0 = { acc[mt][nt][0] + bx, acc[mt][nt][1] + by };
                float2 o1 = { acc[mt][nt][2] + bx, acc[mt][nt][3] + by };
                *(float2*)(C + (size_t)row0 * N + n) = o0;
                *(float2*)(C + (size_t)row1 * N + n) = o1;
            }
        }
    }
}

// ---------------------------------------------------------------------------
// Flash attention, tf32 mma.sync, pre-rounded inputs, 2-stage cp.async K/V,
// exp2-domain softmax, warp-level causal skip (R10 known-good).
// ---------------------------------------------------------------------------
#define FK_TILE  (64 * 68)
#define FV_TILE  (64 * 72)
#define FLASH_SMEM ((2 * FK_TILE + 2 * FV_TILE + 128 * 68) * 4)

__global__ __launch_bounds__(256, 2) void flash_mma()
{
    extern __shared__ float sm[];
    float* Vb = sm + 2 * FK_TILE;
    float* Ps = sm + 2 * FK_TILE + 2 * FV_TILE;    // [128][68]: Q staging, then P
    const uint32_t smb = smem_u32(sm);
    const uint32_t vmb = smem_u32(Vb);

    const int tid  = threadIdx.x;
    const int w    = tid >> 5;
    const int lane = tid & 31;
    const int g    = lane >> 2;
    const int t    = lane & 3;
    const int qt   = (int)gridDim.x - 1 - (int)blockIdx.x;  // heavy CTAs first
    const int h    = blockIdx.y;
    const int b    = blockIdx.z;
    const int q_base = qt * 128;
    const int mb     = w * 16;

    const float* Qg = g_qkv + ((size_t)((0 * BB + b) * NH + h) * TT) * HD;
    const float* Kg = g_qkv + ((size_t)((1 * BB + b) * NH + h) * TT) * HD;
    const float* Vg = g_qkv + ((size_t)((2 * BB + b) * NH + h) * TT) * HD;

    int frow[4], fc4[4];
#pragma unroll
    for (int j = 0; j < 4; j++) {
        const int v = tid + 256 * j;
        frow[j] = v >> 4;
        fc4[j]  = (v & 15) * 4;
    }

    auto issue_kv = [&](int kt) {
        const int s = kt & 1;
        const uint32_t kb = smb + (uint32_t)(s * FK_TILE) * 4u;
        const uint32_t vb = vmb + (uint32_t)(s * FV_TILE) * 4u;
        const float* Kt = Kg + (size_t)(kt * 64) * HD;
        const float* Vt = Vg + (size_t)(kt * 64) * HD;
#pragma unroll
        for (int j = 0; j < 4; j++) {
            const size_t go = (size_t)frow[j] * HD + fc4[j];
            cpa16(kb + (uint32_t)(frow[j] * 68 + fc4[j]) * 4u, Kt + go);
            cpa16(vb + (uint32_t)(frow[j] * 72 + fc4[j]) * 4u, Vt + go);
        }
    };

    issue_kv(0); CP_COMMIT();

    // stage Q tile, prescaled by (1/sqrt(64)) * log2(e) and tf32-rounded.
    const float QS = 0.18033688011112042f;  // 0.125 * log2(e)
    for (int i = tid; i < 2048; i += 256) {
        const int row = i >> 4, c4 = (i & 15) * 4;
        float4 v = *(const float4*)(Qg + (size_t)(q_base + row) * HD + c4);
        v.x = to_tf32(v.x * QS); v.y = to_tf32(v.y * QS);
        v.z = to_tf32(v.z * QS); v.w = to_tf32(v.w * QS);
        *(float4*)&Ps[row * 68 + c4] = v;
    }
    __syncthreads();

    uint32_t qa[8][4];
#pragma unroll
    for (int ks = 0; ks < 8; ks++) {
        const int kb = ks * 8;
        qa[ks][0] = __float_as_uint(Ps[(mb + g) * 68 + kb + t]);
        qa[ks][1] = __float_as_uint(Ps[(mb + g + 8) * 68 + kb + t]);
        qa[ks][2] = __float_as_uint(Ps[(mb + g) * 68 + kb + t + 4]);
        qa[ks][3] = __float_as_uint(Ps[(mb + g + 8) * 68 + kb + t + 4]);
    }

    float oacc[8][4];
#pragma unroll
    for (int nt = 0; nt < 8; nt++)
#pragma unroll
        for (int r = 0; r < 4; r++) oacc[nt][r] = 0.f;
    float m0 = -1e30f, m1 = -1e30f, l0 = 0.f, l1 = 0.f;
    const int r0 = q_base + mb + g, r1 = r0 + 8;

    const int nkt = 2 * qt + 2;
    for (int kt = 0; kt < nkt; kt++) {
        const int st = kt & 1;
        float* Ks = sm + st * FK_TILE;
        float* Vs = Vb + st * FV_TILE;

        CP_WAIT0();
        __syncthreads();   // tile kt visible; all warps done with stage st^1

        if (kt + 1 < nkt) issue_kv(kt + 1);
        CP_COMMIT();

        // warp-level causal skip (bit-exact: tile fully masked for this warp)
        if (kt * 64 > q_base + mb + 15) continue;

        // S = Q @ K^T   (16x64 per warp)
        float sacc[8][4];
#pragma unroll
        for (int nt = 0; nt < 8; nt++)
#pragma unroll
            for (int r = 0; r < 4; r++) sacc[nt][r] = 0.f;
#pragma unroll
        for (int ks = 0; ks < 8; ks++) {
            const int kb = ks * 8;
            uint32_t bf[8][2];
#pragma unroll
            for (int nt = 0; nt < 8; nt++) {
                bf[nt][0] = __float_as_uint(Ks[(nt * 8 + g) * 68 + kb + t]);
                bf[nt][1] = __float_as_uint(Ks[(nt * 8 + g) * 68 + kb + t + 4]);
            }
#pragma unroll
            for (int nt = 0; nt < 8; nt++)
                mma_tf32(sacc[nt][0], sacc[nt][1], sacc[nt][2], sacc[nt][3],
                         qa[ks][0], qa[ks][1], qa[ks][2], qa[ks][3],
                         bf[nt][0], bf[nt][1]);
        }

        if (kt >= 2 * qt) {
            const int sb = kt * 64;
#pragma unroll
            for (int nt = 0; nt < 8; nt++) {
                const int c0 = sb + nt * 8 + 2 * t, c1 = c0 + 1;
                if (c0 > r0) sacc[nt][0] = -1e30f;
                if (c1 > r0) sacc[nt][1] = -1e30f;
                if (c0 > r1) sacc[nt][2] = -1e30f;
                if (c1 > r1) sacc[nt][3] = -1e30f;
            }
        }

        float mx0 = -1e30f, mx1 = -1e30f;
#pragma unroll
        for (int nt = 0; nt < 8; nt++) {
            mx0 = fmaxf(mx0, fmaxf(sacc[nt][0], sacc[nt][1]));
            mx1 = fmaxf(mx1, fmaxf(sacc[nt][2], sacc[nt][3]));
        }
        mx0 = fmaxf(mx0, __shfl_xor_sync(0xffffffffu, mx0, 1));
        mx0 = fmaxf(mx0, __shfl_xor_sync(0xffffffffu, mx0, 2));
        mx1 = fmaxf(mx1, __shfl_xor_sync(0xffffffffu, mx1, 1));
        mx1 = fmaxf(mx1, __shfl_xor_sync(0xffffffffu, mx1, 2));

        const float mn0 = fmaxf(m0, mx0), mn1 = fmaxf(m1, mx1);
        const float f0 = ex2(m0 - mn0), f1 = ex2(m1 - mn1);
        float ls0 = 0.f, ls1 = 0.f;
#pragma unroll
        for (int nt = 0; nt < 8; nt++) {
            const float p00 = ex2(sacc[nt][0] - mn0);
            const float p01 = ex2(sacc[nt][1] - mn0);
            const float p10 = ex2(sacc[nt][2] - mn1);
            const float p11 = ex2(sacc[nt][3] - mn1);
            ls0 += p00 + p01;
            ls1 += p10 + p11;
            float2 s0 = { to_tf32(p00), to_tf32(p01) };
            float2 s1 = { to_tf32(p10), to_tf32(p11) };
            *(float2*)&Ps[(mb + g) * 68 + nt * 8 + 2 * t]     = s0;
            *(float2*)&Ps[(mb + g + 8) * 68 + nt * 8 + 2 * t] = s1;
        }
        ls0 += __shfl_xor_sync(0xffffffffu, ls0, 1);
        ls0 += __shfl_xor_sync(0xffffffffu, ls0, 2);
        ls1 += __shfl_xor_sync(0xffffffffu, ls1, 1);
        ls1 += __shfl_xor_sync(0xffffffffu, ls1, 2);
        l0 = l0 * f0 + ls0;
        l1 = l1 * f1 + ls1;
        m0 = mn0; m1 = mn1;
#pragma unroll
        for (int nt = 0; nt < 8; nt++) {
            oacc[nt][0] *= f0; oacc[nt][1] *= f0;
            oacc[nt][2] *= f1; oacc[nt][3] *= f1;
        }
        __syncwarp();   // P rows are private to this warp

        // O += P @ V
#pragma unroll
        for (int ks = 0; ks < 8; ks++) {
            const int kb = ks * 8;
            uint32_t pa[4];
            pa[0] = __float_as_uint(Ps[(mb + g) * 68 + kb + t]);
            pa[1] = __float_as_uint(Ps[(mb + g + 8) * 68 + kb + t]);
            pa[2] = __float_as_uint(Ps[(mb + g) * 68 + kb + t + 4]);
            pa[3] = __float_as_uint(Ps[(mb + g + 8) * 68 + kb + t + 4]);
            uint32_t bf[8][2];
#pragma unroll
            for (int nt = 0; nt < 8; nt++) {
                bf[nt][0] = __float_as_uint(Vs[(kb + t) * 72 + nt * 8 + g]);
                bf[nt][1] = __float_as_uint(Vs[(kb + t + 4) * 72 + nt * 8 + g]);
            }
#pragma unroll
            for (int nt = 0; nt < 8; nt++)
                mma_tf32(oacc[nt][0], oacc[nt][1], oacc[nt][2], oacc[nt][3],
                         pa[0], pa[1], pa[2], pa[3], bf[nt][0], bf[nt][1]);
        }
    }

    // epilogue: tf32-round (proj GEMM rounds anyway -> identical numerics)
    const float i0 = 1.0f / l0, i1 = 1.0f / l1;
    float* O0 = g_att + ((size_t)(b * TT + r0) * NH + h) * HD;
    float* O1 = g_att + ((size_t)(b * TT + r1) * NH + h) * HD;
#pragma unroll
    for (int nt = 0; nt < 8; nt++) {
        const int d = nt * 8 + 2 * t;
        float2 o0 = { to_tf32(oacc[nt][0] * i0), to_tf32(oacc[nt][1] * i0) };
        float2 o1 = { to_tf32(oacc[nt][2] * i1), to_tf32(oacc[nt][3] * i1) };
        *(float2*)(O0 + d) = o0;
        *(float2*)(O1 + d) = o1;
    }
}

// ---------------------------------------------------------------------------
// kernel_launch
// ---------------------------------------------------------------------------
extern "C" void kernel_launch(void* const* d_in, const int* in_sizes, int n_in,
                              void* d_out, int out_size)
{
    const float* x      = (const float*)d_in[0];
    const float* w_qkv  = (const float*)d_in[1];
    const float* b_qkv  = (const float*)d_in[2];
    const float* w_proj = (const float*)d_in[3];
    const float* b_proj = (const float*)d_in[4];
    float* out = (float*)d_out;

    const int M = BB * TT;  // 4096

    cudaFuncSetAttribute(mma_gemm<0>, cudaFuncAttributeMaxDynamicSharedMemorySize, GSMEM_BYTES);
    cudaFuncSetAttribute(mma_gemm<1>, cudaFuncAttributeMaxDynamicSharedMemorySize, GSMEM_BYTES);
    cudaFuncSetAttribute(flash_mma, cudaFuncAttributeMaxDynamicSharedMemorySize, FLASH_SMEM);

    // 0) merged prepass: tf32-round x, w_qkv, w_proj (one launch)
    round_all<<<1024, 256>>>(x, w_qkv, w_proj);

    // 1) QKV projection (tf32 mma.sync, BK=32, 3-stage cp.async) -> g_qkv
    mma_gemm<0><<<dim3(3 * DM / 128, M / 128), 256, GSMEM_BYTES>>>(b_qkv, nullptr, M, 3 * DM, DM);

    // 2) causal flash attention (tf32 mma.sync, cp.async K/V, exp2 softmax,
    //    warp-level causal skip) -> g_att
    flash_mma<<<dim3(TT / 128, NH, BB), 256, FLASH_SMEM>>>();

    // 3) output projection -> out
    mma_gemm<1><<<dim3(DM / 128, M / 128), 256, GSMEM_BYTES>>>(b_proj, out, M, DM, DM);
}

// round 14
// speedup vs baseline: 1.8627x; 1.7376x over previous
#include <cuda_runtime.h>
#include <cuda_fp16.h>
#include <cstdint>

// Problem constants
#define DM   1024
#define NH   16
#define HD   64
#define BB   2
#define TT   2048

// Scratch (device globals: allocation-free rule). 16B-aligned for vector/cp.async.
// g_qkv: Q,K regions [w][b][h][t][d]; V region stored TRANSPOSED [b][h][d][t].
__device__ __align__(16) __half g_qkv[3 * BB * NH * TT * HD];
__device__ __align__(16) __half g_att[BB * TT * DM];    // [b][t][h][d]
__device__ __align__(16) __half g_xr[BB * TT * DM];     // x rounded
__device__ __align__(16) __half g_wqT[3 * DM * DM];     // w_qkv^T  [n][k]
__device__ __align__(16) __half g_wpT[DM * DM];         // w_proj^T [n][k]

// ---------------------------------------------------------------------------
// helpers
// ---------------------------------------------------------------------------
__device__ __forceinline__ float ex2(float x) {
    float r;
    asm("ex2.approx.f32 %0, %1;" : "=f"(r) : "f"(x));
    return r;
}

__device__ __forceinline__ void mma_f16(float& c0, float& c1, float& c2, float& c3,
                                        uint32_t a0, uint32_t a1, uint32_t a2, uint32_t a3,
                                        uint32_t b0, uint32_t b1) {
    asm volatile(
        "mma.sync.aligned.m16n8k16.row.col.f32.f16.f16.f32 "
        "{%0,%1,%2,%3}, {%4,%5,%6,%7}, {%8,%9}, {%0,%1,%2,%3};"
        : "+f"(c0), "+f"(c1), "+f"(c2), "+f"(c3)
        : "r"(a0), "r"(a1), "r"(a2), "r"(a3), "r"(b0), "r"(b1));
}

__device__ __forceinline__ uint32_t smem_u32(const void* p) {
    uint32_t a;
    asm("{ .reg .u64 t; cvta.to.shared.u64 t, %1; cvt.u32.u64 %0, t; }"
        : "=r"(a) : "l"(p));
    return a;
}
__device__ __forceinline__ void cpa16(uint32_t saddr, const void* g) {
    asm volatile("cp.async.cg.shared.global [%0], [%1], 16;"
                 :: "r"(saddr), "l"(g) : "memory");
}
#define CP_COMMIT() asm volatile("cp.async.commit_group;" ::: "memory")
#define CP_WAIT1()  asm volatile("cp.async.wait_group 1;" ::: "memory")
#define CP_WAIT0()  asm volatile("cp.async.wait_group 0;" ::: "memory")

__device__ __forceinline__ uint32_t pack_h2(float a, float b) {
    __half2 h = __floats2half2_rn(a, b);
    return *(uint32_t*)&h;
}

// ---------------------------------------------------------------------------
// Prepass 1: round x -> half
// ---------------------------------------------------------------------------
__global__ __launch_bounds__(256) void round_x_k(const float* __restrict__ x)
{
    const int n8 = BB * TT * DM / 8;
    const int stride = gridDim.x * blockDim.x;
    for (int i = blockIdx.x * blockDim.x + threadIdx.x; i < n8; i += stride) {
        float4 a = *(const float4*)(x + (size_t)i * 8);
        float4 b = *(const float4*)(x + (size_t)i * 8 + 4);
        uint4 o = { pack_h2(a.x, a.y), pack_h2(a.z, a.w),
                    pack_h2(b.x, b.y), pack_h2(b.z, b.w) };
        *(uint4*)((__half*)g_xr + (size_t)i * 8) = o;
    }
}

// ---------------------------------------------------------------------------
// Prepass 2: transpose + round weights.  src [R=K][C=N] fp32 -> dst [N][K] half
// ---------------------------------------------------------------------------
template <int MODE>
__global__ __launch_bounds__(256) void transpose_w(const float* __restrict__ src,
                                                   int R, int C)
{
    __shared__ float t[32][33];
    __half* dst = (MODE == 0) ? (__half*)g_wqT : (__half*)g_wpT;
    const int bx = blockIdx.x * 32, by = blockIdx.y * 32;
    const int tx = threadIdx.x, ty = threadIdx.y;
#pragma unroll
    for (int i = 0; i < 32; i += 8)
        t[ty + i][tx] = src[(size_t)(by + ty + i) * C + bx + tx];
    __syncthreads();
#pragma unroll
    for (int i = 0; i < 32; i += 8)
        dst[(size_t)(bx + ty + i) * R + by + tx] = __float2half_rn(t[tx][ty + i]);
}

// ---------------------------------------------------------------------------
// fp16 tensor-core GEMM (m16n8k16): C[M,N] = A[M,K] @ Bt[N,K]^T + bias
// BK=64, 3-stage cp.async.  Stages [128][72] half (word idx = 4g+t: bank-free).
// 8 warps, 32x64 per warp, 64 MMAs per chunk per warp.
// MODE 0: A=g_xr; epilogue -> g_qkv (Q prescaled, V transposed).
// MODE 1: A=g_att; epilogue -> fp32 C.
// ---------------------------------------------------------------------------
#define AS_H (128 * 72)
#define BS_H (128 * 72)
#define GSMEM_BYTES (3 * (AS_H + BS_H) * 2)   // 110592 B -> 2 CTAs/SM

#define QSCALE 0.18033688011112042f   // 0.125 * log2(e)

template <int MODE>
__global__ __launch_bounds__(256, 2) void mma_gemm(const float* __restrict__ bias,
                                                   float* __restrict__ Cout,
                                                   int M, int N, int K)
{
    extern __shared__ char smraw[];
    __half* AsF = (__half*)smraw;
    __half* BsF = AsF + 3 * AS_H;
    const uint32_t abase = smem_u32(AsF);
    const uint32_t bbase = smem_u32(BsF);

    const int tid  = threadIdx.x;
    const int bm   = blockIdx.y * 128;
    const int bn   = blockIdx.x * 128;
    const int w    = tid >> 5;
    const int lane = tid & 31;
    const int g    = lane >> 2;
    const int t    = lane & 3;
    const int m0   = (w & 3) * 32;
    const int n0   = (w >> 2) * 64;

    const __half* Aeff = (MODE == 0) ? (const __half*)g_xr : (const __half*)g_att;
    const __half* Bt   = (MODE == 0) ? (const __half*)g_wqT : (const __half*)g_wpT;

    float acc[2][8][4];
#pragma unroll
    for (int mt = 0; mt < 2; mt++)
#pragma unroll
        for (int nt = 0; nt < 8; nt++)
#pragma unroll
            for (int r = 0; r < 4; r++) acc[mt][nt][r] = 0.f;

    int crow[4], ccol[4];
#pragma unroll
    for (int j = 0; j < 4; j++) {
        const int f = tid + 256 * j;
        crow[j] = f >> 3;          // 0..127
        ccol[j] = (f & 7) * 8;     // half offset, 16B units
    }

    const int NC = K >> 6;   // 16

    auto issue = [&](int c) {
        const int s = c % 3;
        const int k0 = c << 6;
#pragma unroll
        for (int j = 0; j < 4; j++) {
            cpa16(abase + (uint32_t)(s * AS_H + crow[j] * 72 + ccol[j]) * 2u,
                  Aeff + (size_t)(bm + crow[j]) * K + k0 + ccol[j]);
            cpa16(bbase + (uint32_t)(s * BS_H + crow[j] * 72 + ccol[j]) * 2u,
                  Bt + (size_t)(bn + crow[j]) * K + k0 + ccol[j]);
        }
    };

    issue(0); CP_COMMIT();
    issue(1); CP_COMMIT();

    for (int c = 0; c < NC; c++) {
        const int st = c % 3;
        CP_WAIT1();
        __syncthreads();

        if (c + 2 < NC) issue(c + 2);
        CP_COMMIT();

        const __half* As = AsF + st * AS_H;
        const __half* Bs = BsF + st * BS_H;
#pragma unroll
        for (int ks = 0; ks < 4; ks++) {
            const int kb = ks * 16;
            uint32_t af[2][4], bf[8][2];
#pragma unroll
            for (int mt = 0; mt < 2; mt++) {
                const int m = m0 + mt * 16 + g;
                af[mt][0] = *(const uint32_t*)&As[m * 72 + kb + 2 * t];
                af[mt][1] = *(const uint32_t*)&As[(m + 8) * 72 + kb + 2 * t];
                af[mt][2] = *(const uint32_t*)&As[m * 72 + kb + 2 * t + 8];
                af[mt][3] = *(const uint32_t*)&As[(m + 8) * 72 + kb + 2 * t + 8];
            }
#pragma unroll
            for (int nt = 0; nt < 8; nt++) {
                const int n = n0 + nt * 8 + g;
                bf[nt][0] = *(const uint32_t*)&Bs[n * 72 + kb + 2 * t];
                bf[nt][1] = *(const uint32_t*)&Bs[n * 72 + kb + 2 * t + 8];
            }
#pragma unroll
            for (int mt = 0; mt < 2; mt++)
#pragma unroll
                for (int nt = 0; nt < 8; nt++)
                    mma_f16(acc[mt][nt][0], acc[mt][nt][1],
                            acc[mt][nt][2], acc[mt][nt][3],
                            af[mt][0], af[mt][1], af[mt][2], af[mt][3],
                            bf[nt][0], bf[nt][1]);
        }
    }

    const int ng = bn + n0;
    if (MODE == 0) {
        const int which = ng >> 10;
        const int rem   = ng & 1023;
        const int h     = rem >> 6;
#pragma unroll
        for (int mt = 0; mt < 2; mt++) {
            const int row0 = bm + m0 + mt * 16 + g;
            const int row1 = row0 + 8;
            const int b0i = row0 >> 11, t0i = row0 & 2047;
            const int b1i = row1 >> 11, t1i = row1 & 2047;
            if (which < 2) {
                __half* base0 = (__half*)g_qkv
                    + ((size_t)((which * BB + b0i) * NH + h) * TT + t0i) * HD;
                __half* base1 = (__half*)g_qkv
                    + ((size_t)((which * BB + b1i) * NH + h) * TT + t1i) * HD;
                const float sc = (which == 0) ? QSCALE : 1.0f;
#pragma unroll
                for (int nt = 0; nt < 8; nt++) {
                    const int d = nt * 8 + 2 * t;
                    const float bx = bias[ng + d], by = bias[ng + d + 1];
                    *(uint32_t*)&base0[d] = pack_h2((acc[mt][nt][0] + bx) * sc,
                                                    (acc[mt][nt][1] + by) * sc);
                    *(uint32_t*)&base1[d] = pack_h2((acc[mt][nt][2] + bx) * sc,
                                                    (acc[mt][nt][3] + by) * sc);
                }
            } else {
                // V: transposed store [b][h][d][t]
                __half* vb0 = (__half*)g_qkv
                    + (size_t)((2 * BB + b0i) * NH + h) * HD * TT;
                __half* vb1 = (__half*)g_qkv
                    + (size_t)((2 * BB + b1i) * NH + h) * HD * TT;
#pragma unroll
                for (int nt = 0; nt < 8; nt++) {
                    const int d = nt * 8 + 2 * t;
                    const float bx = bias[ng + d], by = bias[ng + d + 1];
                    vb0[(size_t)d * TT + t0i]       = __float2half_rn(acc[mt][nt][0] + bx);
                    vb0[(size_t)(d + 1) * TT + t0i] = __float2half_rn(acc[mt][nt][1] + by);
                    vb1[(size_t)d * TT + t1i]       = __float2half_rn(acc[mt][nt][2] + bx);
                    vb1[(size_t)(d + 1) * TT + t1i] = __float2half_rn(acc[mt][nt][3] + by);
                }
            }
        }
    } else {
#pragma unroll
        for (int mt = 0; mt < 2; mt++) {
            const int row0 = bm + m0 + mt * 16 + g;
            const int row1 = row0 + 8;
#pragma unroll
            for (int nt = 0; nt < 8; nt++) {
                const int n = ng + nt * 8 + 2 * t;
                const float bx = bias[n], by = bias[n + 1];
                float2 o0 = { acc[mt][nt][0] + bx, acc[mt][nt][1] + by };
                float2 o1 = { acc[mt][nt][2] + bx, acc[mt][nt][3] + by };
                *(float2*)(Cout + (size_t)row0 * N + n) = o0;
                *(float2*)(Cout + (size_t)row1 * N + n) = o1;
            }
        }
    }
}

// ---------------------------------------------------------------------------
// Flash attention, fp16 m16n8k16, fp32 accumulate/softmax (exp2 domain),
// 2-stage cp.async K/V, warp-level causal skip, heavy CTAs first.
// K consumed [s][d] (natural); V consumed transposed [d][t] (written by GEMM).
// ---------------------------------------------------------------------------
#define FK_H (64 * 72)
#define FV_H (64 * 72)
#define FQ_H (128 * 72)
#define FLASH_SMEM ((2 * FK_H + 2 * FV_H + FQ_H) * 2)   // 55296 B

__global__ __launch_bounds__(256, 2) void flash_mma()
{
    extern __shared__ char smraw[];
    __half* Kb = (__half*)smraw;                 // 2 stages [64][72]
    __half* Vb = Kb + 2 * FK_H;                  // 2 stages [64][72] (rows = d)
    __half* Ps = Vb + 2 * FV_H;                  // [128][72]: Q staging, then P
    const uint32_t kmb = smem_u32(Kb);
    const uint32_t vmb = smem_u32(Vb);
    const uint32_t pmb = smem_u32(Ps);

    const int tid  = threadIdx.x;
    const int w    = tid >> 5;
    const int lane = tid & 31;
    const int g    = lane >> 2;
    const int t    = lane & 3;
    const int qt   = (int)gridDim.x - 1 - (int)blockIdx.x;
    const int h    = blockIdx.y;
    const int b    = blockIdx.z;
    const int q_base = qt * 128;
    const int mb     = w * 16;

    const __half* Qg = (const __half*)g_qkv + (size_t)((0 * BB + b) * NH + h) * TT * HD;
    const __half* Kg = (const __half*)g_qkv + (size_t)((1 * BB + b) * NH + h) * TT * HD;
    const __half* Vt = (const __half*)g_qkv + (size_t)((2 * BB + b) * NH + h) * HD * TT;

    auto issue_kv = [&](int kt) {
        const int s = kt & 1;
#pragma unroll
        for (int j = 0; j < 2; j++) {
            const int v = tid + 256 * j;
            const int row = v >> 3;          // 0..63
            const int c8  = (v & 7) * 8;     // half offset
            cpa16(kmb + (uint32_t)(s * FK_H + row * 72 + c8) * 2u,
                  Kg + (size_t)(kt * 64 + row) * HD + c8);
            cpa16(vmb + (uint32_t)(s * FV_H + row * 72 + c8) * 2u,
                  Vt + (size_t)row * TT + kt * 64 + c8);
        }
    };

    // stage Q (pure copy: already half + prescaled by GEMM epilogue)
#pragma unroll
    for (int j = 0; j < 4; j++) {
        const int v = tid + 256 * j;
        const int row = v >> 3;
        const int c8  = (v & 7) * 8;
        cpa16(pmb + (uint32_t)(row * 72 + c8) * 2u,
              Qg + (size_t)(q_base + row) * HD + c8);
    }
    issue_kv(0);
    CP_COMMIT();
    CP_WAIT0();
    __syncthreads();

    uint32_t qa[4][4];
#pragma unroll
    for (int ks = 0; ks < 4; ks++) {
        const int kb = ks * 16;
        qa[ks][0] = *(const uint32_t*)&Ps[(mb + g) * 72 + kb + 2 * t];
        qa[ks][1] = *(const uint32_t*)&Ps[(mb + g + 8) * 72 + kb + 2 * t];
        qa[ks][2] = *(const uint32_t*)&Ps[(mb + g) * 72 + kb + 2 * t + 8];
        qa[ks][3] = *(const uint32_t*)&Ps[(mb + g + 8) * 72 + kb + 2 * t + 8];
    }

    float oacc[8][4];
#pragma unroll
    for (int nt = 0; nt < 8; nt++)
#pragma unroll
        for (int r = 0; r < 4; r++) oacc[nt][r] = 0.f;
    float m0 = -1e30f, m1 = -1e30f, l0 = 0.f, l1 = 0.f;
    const int r0 = q_base + mb + g, r1 = r0 + 8;

    const int nkt = 2 * qt + 2;
    for (int kt = 0; kt < nkt; kt++) {
        const int st = kt & 1;
        const __half* Ks = Kb + st * FK_H;
        const __half* Vs = Vb + st * FV_H;

        CP_WAIT0();
        __syncthreads();   // tile kt visible; all warps done with stage st^1

        if (kt + 1 < nkt) issue_kv(kt + 1);
        CP_COMMIT();

        // warp-level causal skip (bit-exact: tile fully masked for this warp)
        if (kt * 64 > q_base + mb + 15) continue;

        // S = Q @ K^T   (16x64 per warp)
        float sacc[8][4];
#pragma unroll
        for (int nt = 0; nt < 8; nt++)
#pragma unroll
            for (int r = 0; r < 4; r++) sacc[nt][r] = 0.f;
#pragma unroll
        for (int ks = 0; ks < 4; ks++) {
            const int kb = ks * 16;
            uint32_t bf[8][2];
#pragma unroll
            for (int nt = 0; nt < 8; nt++) {
                bf[nt][0] = *(const uint32_t*)&Ks[(nt * 8 + g) * 72 + kb + 2 * t];
                bf[nt][1] = *(const uint32_t*)&Ks[(nt * 8 + g) * 72 + kb + 2 * t + 8];
            }
#pragma unroll
            for (int nt = 0; nt < 8; nt++)
                mma_f16(sacc[nt][0], sacc[nt][1], sacc[nt][2], sacc[nt][3],
                        qa[ks][0], qa[ks][1], qa[ks][2], qa[ks][3],
                        bf[nt][0], bf[nt][1]);
        }

        if (kt >= 2 * qt) {
            const int sb = kt * 64;
#pragma unroll
            for (int nt = 0; nt < 8; nt++) {
                const int c0 = sb + nt * 8 + 2 * t, c1 = c0 + 1;
                if (c0 > r0) sacc[nt][0] = -1e30f;
                if (c1 > r0) sacc[nt][1] = -1e30f;
                if (c0 > r1) sacc[nt][2] = -1e30f;
                if (c1 > r1) sacc[nt][3] = -1e30f;
            }
        }

        float mx0 = -1e30f, mx1 = -1e30f;
#pragma unroll
        for (int nt = 0; nt < 8; nt++) {
            mx0 = fmaxf(mx0, fmaxf(sacc[nt][0], sacc[nt][1]));
            mx1 = fmaxf(mx1, fmaxf(sacc[nt][2], sacc[nt][3]));
        }
        mx0 = fmaxf(mx0, __shfl_xor_sync(0xffffffffu, mx0, 1));
        mx0 = fmaxf(mx0, __shfl_xor_sync(0xffffffffu, mx0, 2));
        mx1 = fmaxf(mx1, __shfl_xor_sync(0xffffffffu, mx1, 1));
        mx1 = fmaxf(mx1, __shfl_xor_sync(0xffffffffu, mx1, 2));

        const float mn0 = fmaxf(m0, mx0), mn1 = fmaxf(m1, mx1);
        const float f0 = ex2(m0 - mn0), f1 = ex2(m1 - mn1);
        float ls0 = 0.f, ls1 = 0.f;
#pragma unroll
        for (int nt = 0; nt < 8; nt++) {
            const float p00 = ex2(sacc[nt][0] - mn0);
            const float p01 = ex2(sacc[nt][1] - mn0);
            const float p10 = ex2(sacc[nt][2] - mn1);
            const float p11 = ex2(sacc[nt][3] - mn1);
            ls0 += p00 + p01;
            ls1 += p10 + p11;
            *(uint32_t*)&Ps[(mb + g) * 72 + nt * 8 + 2 * t]     = pack_h2(p00, p01);
            *(uint32_t*)&Ps[(mb + g + 8) * 72 + nt * 8 + 2 * t] = pack_h2(p10, p11);
        }
        ls0 += __shfl_xor_sync(0xffffffffu, ls0, 1);
        ls0 += __shfl_xor_sync(0xffffffffu, ls0, 2);
        ls1 += __shfl_xor_sync(0xffffffffu, ls1, 1);
        ls1 += __shfl_xor_sync(0xffffffffu, ls1, 2);
        l0 = l0 * f0 + ls0;
        l1 = l1 * f1 + ls1;
        m0 = mn0; m1 = mn1;
#pragma unroll
        for (int nt = 0; nt < 8; nt++) {
            oacc[nt][0] *= f0; oacc[nt][1] *= f0;
            oacc[nt][2] *= f1; oacc[nt][3] *= f1;
        }
        __syncwarp();   // P rows are private to this warp

        // O += P @ V   (V^T tile: rows d, cols s)
#pragma unroll
        for (int ks = 0; ks < 4; ks++) {
            const int kb = ks * 16;
            uint32_t pa[4];
            pa[0] = *(const uint32_t*)&Ps[(mb + g) * 72 + kb + 2 * t];
            pa[1] = *(const uint32_t*)&Ps[(mb + g + 8) * 72 + kb + 2 * t];
            pa[2] = *(const uint32_t*)&Ps[(mb + g) * 72 + kb + 2 * t + 8];
            pa[3] = *(const uint32_t*)&Ps[(mb + g + 8) * 72 + kb + 2 * t + 8];
            uint32_t bf[8][2];
#pragma unroll
            for (int nt = 0; nt < 8; nt++) {
                bf[nt][0] = *(const uint32_t*)&Vs[(nt * 8 + g) * 72 + kb + 2 * t];
                bf[nt][1] = *(const uint32_t*)&Vs[(nt * 8 + g) * 72 + kb + 2 * t + 8];
            }
#pragma unroll
            for (int nt = 0; nt < 8; nt++)
                mma_f16(oacc[nt][0], oacc[nt][1], oacc[nt][2], oacc[nt][3],
                        pa[0], pa[1], pa[2], pa[3], bf[nt][0], bf[nt][1]);
        }
    }

    // epilogue -> g_att half [b][t][h][d]
    const float i0 = 1.0f / l0, i1 = 1.0f / l1;
    __half* O0 = (__half*)g_att + ((size_t)(b * TT + r0) * NH + h) * HD;
    __half* O1 = (__half*)g_att + ((size_t)(b * TT + r1) * NH + h) * HD;
#pragma unroll
    for (int nt = 0; nt < 8; nt++) {
        const int d = nt * 8 + 2 * t;
        *(uint32_t*)&O0[d] = pack_h2(oacc[nt][0] * i0, oacc[nt][1] * i0);
        *(uint32_t*)&O1[d] = pack_h2(oacc[nt][2] * i1, oacc[nt][3] * i1);
    }
}

// ---------------------------------------------------------------------------
// kernel_launch
// ---------------------------------------------------------------------------
extern "C" void kernel_launch(void* const* d_in, const int* in_sizes, int n_in,
                              void* d_out, int out_size)
{
    const float* x      = (const float*)d_in[0];
    const float* w_qkv  = (const float*)d_in[1];
    const float* b_qkv  = (const float*)d_in[2];
    const float* w_proj = (const float*)d_in[3];
    const float* b_proj = (const float*)d_in[4];
    float* out = (float*)d_out;

    const int M = BB * TT;  // 4096

    cudaFuncSetAttribute(mma_gemm<0>, cudaFuncAttributeMaxDynamicSharedMemorySize, GSMEM_BYTES);
    cudaFuncSetAttribute(mma_gemm<1>, cudaFuncAttributeMaxDynamicSharedMemorySize, GSMEM_BYTES);
    cudaFuncSetAttribute(flash_mma, cudaFuncAttributeMaxDynamicSharedMemorySize, FLASH_SMEM);

    // 0) prepass: round x; transpose+round weights to [N][K] half
    round_x_k<<<512, 256>>>(x);
    transpose_w<0><<<dim3(3 * DM / 32, DM / 32), dim3(32, 8)>>>(w_qkv, DM, 3 * DM);
    transpose_w<1><<<dim3(DM / 32, DM / 32), dim3(32, 8)>>>(w_proj, DM, DM);

    // 1) QKV projection (fp16 m16n8k16, BK=64, 3-stage cp.async) -> g_qkv
    mma_gemm<0><<<dim3(3 * DM / 128, M / 128), 256, GSMEM_BYTES>>>(b_qkv, nullptr, M, 3 * DM, DM);

    // 2) causal flash attention (fp16 MMA, fp32 softmax) -> g_att
    flash_mma<<<dim3(TT / 128, NH, BB), 256, FLASH_SMEM>>>();

    // 3) output projection -> out (fp32)
    mma_gemm<1><<<dim3(DM / 128, M / 128), 256, GSMEM_BYTES>>>(b_proj, out, M, DM, DM);
}

// round 16
// speedup vs baseline: 2.0033x; 1.0755x over previous
#include <cuda_runtime.h>
#include <cuda_fp16.h>
#include <cstdint>

// Problem constants
#define DM   1024
#define NH   16
#define HD   64
#define BB   2
#define TT   2048

// Scratch (device globals: allocation-free rule). 16B-aligned for vector/cp.async.
// g_qkv: Q,K regions [w][b][h][t][d]; V region stored TRANSPOSED [b][h][d][t].
__device__ __align__(16) __half g_qkv[3 * BB * NH * TT * HD];
__device__ __align__(16) __half g_att[BB * TT * DM];    // [b][t][h][d]
__device__ __align__(16) __half g_xr[BB * TT * DM];     // x rounded
__device__ __align__(16) __half g_wqT[3 * DM * DM];     // w_qkv^T  [n][k]
__device__ __align__(16) __half g_wpT[DM * DM];         // w_proj^T [n][k]

// ---------------------------------------------------------------------------
// helpers
// ---------------------------------------------------------------------------
__device__ __forceinline__ float ex2(float x) {
    float r;
    asm("ex2.approx.f32 %0, %1;" : "=f"(r) : "f"(x));
    return r;
}

__device__ __forceinline__ void mma_f16(float& c0, float& c1, float& c2, float& c3,
                                        uint32_t a0, uint32_t a1, uint32_t a2, uint32_t a3,
                                        uint32_t b0, uint32_t b1) {
    asm volatile(
        "mma.sync.aligned.m16n8k16.row.col.f32.f16.f16.f32 "
        "{%0,%1,%2,%3}, {%4,%5,%6,%7}, {%8,%9}, {%0,%1,%2,%3};"
        : "+f"(c0), "+f"(c1), "+f"(c2), "+f"(c3)
        : "r"(a0), "r"(a1), "r"(a2), "r"(a3), "r"(b0), "r"(b1));
}

__device__ __forceinline__ void ldsm4(uint32_t& r0, uint32_t& r1,
                                      uint32_t& r2, uint32_t& r3, uint32_t addr) {
    asm volatile("ldmatrix.sync.aligned.m8n8.x4.shared.b16 {%0,%1,%2,%3}, [%4];"
                 : "=r"(r0), "=r"(r1), "=r"(r2), "=r"(r3) : "r"(addr));
}

__device__ __forceinline__ uint32_t smem_u32(const void* p) {
    uint32_t a;
    asm("{ .reg .u64 t; cvta.to.shared.u64 t, %1; cvt.u32.u64 %0, t; }"
        : "=r"(a) : "l"(p));
    return a;
}
__device__ __forceinline__ void cpa16(uint32_t saddr, const void* g) {
    asm volatile("cp.async.cg.shared.global [%0], [%1], 16;"
                 :: "r"(saddr), "l"(g) : "memory");
}
#define CP_COMMIT() asm volatile("cp.async.commit_group;" ::: "memory")
#define CP_WAIT1()  asm volatile("cp.async.wait_group 1;" ::: "memory")
#define CP_WAIT0()  asm volatile("cp.async.wait_group 0;" ::: "memory")

__device__ __forceinline__ uint32_t pack_h2(float a, float b) {
    __half2 h = __floats2half2_rn(a, b);
    return *(uint32_t*)&h;
}

// ---------------------------------------------------------------------------
// Prepass 1: round x -> half
// ---------------------------------------------------------------------------
__global__ __launch_bounds__(256) void round_x_k(const float* __restrict__ x)
{
    const int n8 = BB * TT * DM / 8;
    const int stride = gridDim.x * blockDim.x;
    for (int i = blockIdx.x * blockDim.x + threadIdx.x; i < n8; i += stride) {
        float4 a = *(const float4*)(x + (size_t)i * 8);
        float4 b = *(const float4*)(x + (size_t)i * 8 + 4);
        uint4 o = { pack_h2(a.x, a.y), pack_h2(a.z, a.w),
                    pack_h2(b.x, b.y), pack_h2(b.z, b.w) };
        *(uint4*)((__half*)g_xr + (size_t)i * 8) = o;
    }
}

// ---------------------------------------------------------------------------
// Prepass 2: transpose + round weights.  src [R=K][C=N] fp32 -> dst [N][K] half
// ---------------------------------------------------------------------------
template <int MODE>
__global__ __launch_bounds__(256) void transpose_w(const float* __restrict__ src,
                                                   int R, int C)
{
    __shared__ float t[32][33];
    __half* dst = (MODE == 0) ? (__half*)g_wqT : (__half*)g_wpT;
    const int bx = blockIdx.x * 32, by = blockIdx.y * 32;
    const int tx = threadIdx.x, ty = threadIdx.y;
#pragma unroll
    for (int i = 0; i < 32; i += 8)
        t[ty + i][tx] = src[(size_t)(by + ty + i) * C + bx + tx];
    __syncthreads();
#pragma unroll
    for (int i = 0; i < 32; i += 8)
        dst[(size_t)(bx + ty + i) * R + by + tx] = __float2half_rn(t[tx][ty + i]);
}

// ---------------------------------------------------------------------------
// fp16 tensor-core GEMM (m16n8k16), BK=64, 3-stage cp.async, ldmatrix frags.
// Stages [128][72] half.  8 warps, 32x64 per warp.
// MODE 0: A=g_xr; epilogue -> g_qkv (Q prescaled, V transposed).
// MODE 1: A=g_att; epilogue -> fp32 C.
// ---------------------------------------------------------------------------
#define AS_H (128 * 72)
#define BS_H (128 * 72)
#define GSMEM_BYTES (3 * (AS_H + BS_H) * 2)   // 110592 B -> 2 CTAs/SM

#define QSCALE 0.18033688011112042f   // 0.125 * log2(e)

template <int MODE>
__global__ __launch_bounds__(256, 2) void mma_gemm(const float* __restrict__ bias,
                                                   float* __restrict__ Cout,
                                                   int M, int N, int K)
{
    extern __shared__ char smraw[];
    __half* AsF = (__half*)smraw;
    __half* BsF = AsF + 3 * AS_H;
    const uint32_t abase = smem_u32(AsF);
    const uint32_t bbase = smem_u32(BsF);

    const int tid  = threadIdx.x;
    const int bm   = blockIdx.y * 128;
    const int bn   = blockIdx.x * 128;
    const int w    = tid >> 5;
    const int lane = tid & 31;
    const int g    = lane >> 2;
    const int t    = lane & 3;
    const int m0   = (w & 3) * 32;
    const int n0   = (w >> 2) * 64;

    // ldmatrix per-lane offsets
    const int a_r = lane & 15;                         // row within 16
    const int a_c = (lane >> 4) * 8;                   // k half
    const int b_r = ((lane >> 4) << 3) + (lane & 7);   // row within 16 (2 n-tiles)
    const int b_c = ((lane >> 3) & 1) * 8;             // k half

    const __half* Aeff = (MODE == 0) ? (const __half*)g_xr : (const __half*)g_att;
    const __half* Bt   = (MODE == 0) ? (const __half*)g_wqT : (const __half*)g_wpT;

    float acc[2][8][4];
#pragma unroll
    for (int mt = 0; mt < 2; mt++)
#pragma unroll
        for (int nt = 0; nt < 8; nt++)
#pragma unroll
            for (int r = 0; r < 4; r++) acc[mt][nt][r] = 0.f;

    int crow[4], ccol[4];
#pragma unroll
    for (int j = 0; j < 4; j++) {
        const int f = tid + 256 * j;
        crow[j] = f >> 3;
        ccol[j] = (f & 7) * 8;
    }

    const int NC = K >> 6;   // 16

    auto issue = [&](int c) {
        const int s = c % 3;
        const int k0 = c << 6;
#pragma unroll
        for (int j = 0; j < 4; j++) {
            cpa16(abase + (uint32_t)(s * AS_H + crow[j] * 72 + ccol[j]) * 2u,
                  Aeff + (size_t)(bm + crow[j]) * K + k0 + ccol[j]);
            cpa16(bbase + (uint32_t)(s * BS_H + crow[j] * 72 + ccol[j]) * 2u,
                  Bt + (size_t)(bn + crow[j]) * K + k0 + ccol[j]);
        }
    };

    issue(0); CP_COMMIT();
    issue(1); CP_COMMIT();

    for (int c = 0; c < NC; c++) {
        const int st = c % 3;
        CP_WAIT1();
        __syncthreads();

        if (c + 2 < NC) issue(c + 2);
        CP_COMMIT();

        const uint32_t as = abase + (uint32_t)(st * AS_H) * 2u;
        const uint32_t bs = bbase + (uint32_t)(st * BS_H) * 2u;
#pragma unroll
        for (int ks = 0; ks < 4; ks++) {
            const int kb = ks * 16;
            uint32_t af[2][4], bf[8][2];
#pragma unroll
            for (int mt = 0; mt < 2; mt++)
                ldsm4(af[mt][0], af[mt][1], af[mt][2], af[mt][3],
                      as + (uint32_t)((m0 + mt * 16 + a_r) * 72 + kb + a_c) * 2u);
#pragma unroll
            for (int p = 0; p < 4; p++)
                ldsm4(bf[2 * p][0], bf[2 * p][1], bf[2 * p + 1][0], bf[2 * p + 1][1],
                      bs + (uint32_t)((n0 + p * 16 + b_r) * 72 + kb + b_c) * 2u);
#pragma unroll
            for (int mt = 0; mt < 2; mt++)
#pragma unroll
                for (int nt = 0; nt < 8; nt++)
                    mma_f16(acc[mt][nt][0], acc[mt][nt][1],
                            acc[mt][nt][2], acc[mt][nt][3],
                            af[mt][0], af[mt][1], af[mt][2], af[mt][3],
                            bf[nt][0], bf[nt][1]);
        }
    }

    const int ng = bn + n0;
    if (MODE == 0) {
        const int which = ng >> 10;
        const int rem   = ng & 1023;
        const int h     = rem >> 6;
#pragma unroll
        for (int mt = 0; mt < 2; mt++) {
            const int row0 = bm + m0 + mt * 16 + g;
            const int row1 = row0 + 8;
            const int b0i = row0 >> 11, t0i = row0 & 2047;
            const int b1i = row1 >> 11, t1i = row1 & 2047;
            if (which < 2) {
                __half* base0 = (__half*)g_qkv
                    + ((size_t)((which * BB + b0i) * NH + h) * TT + t0i) * HD;
                __half* base1 = (__half*)g_qkv
                    + ((size_t)((which * BB + b1i) * NH + h) * TT + t1i) * HD;
                const float sc = (which == 0) ? QSCALE : 1.0f;
#pragma unroll
                for (int nt = 0; nt < 8; nt++) {
                    const int d = nt * 8 + 2 * t;
                    const float bx = bias[ng + d], by = bias[ng + d + 1];
                    *(uint32_t*)&base0[d] = pack_h2((acc[mt][nt][0] + bx) * sc,
                                                    (acc[mt][nt][1] + by) * sc);
                    *(uint32_t*)&base1[d] = pack_h2((acc[mt][nt][2] + bx) * sc,
                                                    (acc[mt][nt][3] + by) * sc);
                }
            } else {
                __half* vb0 = (__half*)g_qkv
                    + (size_t)((2 * BB + b0i) * NH + h) * HD * TT;
                __half* vb1 = (__half*)g_qkv
                    + (size_t)((2 * BB + b1i) * NH + h) * HD * TT;
#pragma unroll
                for (int nt = 0; nt < 8; nt++) {
                    const int d = nt * 8 + 2 * t;
                    const float bx = bias[ng + d], by = bias[ng + d + 1];
                    vb0[(size_t)d * TT + t0i]       = __float2half_rn(acc[mt][nt][0] + bx);
                    vb0[(size_t)(d + 1) * TT + t0i] = __float2half_rn(acc[mt][nt][1] + by);
                    vb1[(size_t)d * TT + t1i]       = __float2half_rn(acc[mt][nt][2] + bx);
                    vb1[(size_t)(d + 1) * TT + t1i] = __float2half_rn(acc[mt][nt][3] + by);
                }
            }
        }
    } else {
#pragma unroll
        for (int mt = 0; mt < 2; mt++) {
            const int row0 = bm + m0 + mt * 16 + g;
            const int row1 = row0 + 8;
#pragma unroll
            for (int nt = 0; nt < 8; nt++) {
                const int n = ng + nt * 8 + 2 * t;
                const float bx = bias[n], by = bias[n + 1];
                float2 o0 = { acc[mt][nt][0] + bx, acc[mt][nt][1] + by };
                float2 o1 = { acc[mt][nt][2] + bx, acc[mt][nt][3] + by };
                *(float2*)(Cout + (size_t)row0 * N + n) = o0;
                *(float2*)(Cout + (size_t)row1 * N + n) = o1;
            }
        }
    }
}

// ---------------------------------------------------------------------------
// Flash attention, fp16 m16n8k16 + ldmatrix, fp32 softmax (exp2 domain),
// 2-stage cp.async K/V, warp-level causal skip, heavy CTAs first.
// K consumed [s][d]; V consumed transposed [d][t] (written by GEMM).
// ---------------------------------------------------------------------------
#define FK_H (64 * 72)
#define FV_H (64 * 72)
#define FQ_H (128 * 72)
#define FLASH_SMEM ((2 * FK_H + 2 * FV_H + FQ_H) * 2)   // 55296 B

__global__ __launch_bounds__(256, 2) void flash_mma()
{
    extern __shared__ char smraw[];
    __half* Kb = (__half*)smraw;
    __half* Vb = Kb + 2 * FK_H;
    __half* Ps = Vb + 2 * FV_H;
    const uint32_t kmb = smem_u32(Kb);
    const uint32_t vmb = smem_u32(Vb);
    const uint32_t pmb = smem_u32(Ps);

    const int tid  = threadIdx.x;
    const int w    = tid >> 5;
    const int lane = tid & 31;
    const int g    = lane >> 2;
    const int t    = lane & 3;
    const int qt   = (int)gridDim.x - 1 - (int)blockIdx.x;
    const int h    = blockIdx.y;
    const int b    = blockIdx.z;
    const int q_base = qt * 128;
    const int mb     = w * 16;

    const int a_r = lane & 15;
    const int a_c = (lane >> 4) * 8;
    const int b_r = ((lane >> 4) << 3) + (lane & 7);
    const int b_c = ((lane >> 3) & 1) * 8;

    const __half* Qg = (const __half*)g_qkv + (size_t)((0 * BB + b) * NH + h) * TT * HD;
    const __half* Kg = (const __half*)g_qkv + (size_t)((1 * BB + b) * NH + h) * TT * HD;
    const __half* Vt = (const __half*)g_qkv + (size_t)((2 * BB + b) * NH + h) * HD * TT;

    auto issue_kv = [&](int kt) {
        const int s = kt & 1;
#pragma unroll
        for (int j = 0; j < 2; j++) {
            const int v = tid + 256 * j;
            const int row = v >> 3;
            const int c8  = (v & 7) * 8;
            cpa16(kmb + (uint32_t)(s * FK_H + row * 72 + c8) * 2u,
                  Kg + (size_t)(kt * 64 + row) * HD + c8);
            cpa16(vmb + (uint32_t)(s * FV_H + row * 72 + c8) * 2u,
                  Vt + (size_t)row * TT + kt * 64 + c8);
        }
    };

    // stage Q (pure copy: already half + prescaled by GEMM epilogue)
#pragma unroll
    for (int j = 0; j < 4; j++) {
        const int v = tid + 256 * j;
        const int row = v >> 3;
        const int c8  = (v & 7) * 8;
        cpa16(pmb + (uint32_t)(row * 72 + c8) * 2u,
              Qg + (size_t)(q_base + row) * HD + c8);
    }
    issue_kv(0);
    CP_COMMIT();
    CP_WAIT0();
    __syncthreads();

    uint32_t qa[4][4];
#pragma unroll
    for (int ks = 0; ks < 4; ks++)
        ldsm4(qa[ks][0], qa[ks][1], qa[ks][2], qa[ks][3],
              pmb + (uint32_t)((mb + a_r) * 72 + ks * 16 + a_c) * 2u);

    float oacc[8][4];
#pragma unroll
    for (int nt = 0; nt < 8; nt++)
#pragma unroll
        for (int r = 0; r < 4; r++) oacc[nt][r] = 0.f;
    float m0 = -1e30f, m1 = -1e30f, l0 = 0.f, l1 = 0.f;
    const int r0 = q_base + mb + g, r1 = r0 + 8;

    const int nkt = 2 * qt + 2;
    for (int kt = 0; kt < nkt; kt++) {
        const int st = kt & 1;
        const uint32_t ks_b = kmb + (uint32_t)(st * FK_H) * 2u;
        const uint32_t vs_b = vmb + (uint32_t)(st * FV_H) * 2u;

        CP_WAIT0();
        __syncthreads();   // tile kt visible; all warps done with stage st^1

        if (kt + 1 < nkt) issue_kv(kt + 1);
        CP_COMMIT();

        // warp-level causal skip (bit-exact: tile fully masked for this warp)
        if (kt * 64 > q_base + mb + 15) continue;

        // S = Q @ K^T   (16x64 per warp)
        float sacc[8][4];
#pragma unroll
        for (int nt = 0; nt < 8; nt++)
#pragma unroll
            for (int r = 0; r < 4; r++) sacc[nt][r] = 0.f;
#pragma unroll
        for (int ks = 0; ks < 4; ks++) {
            const int kb = ks * 16;
            uint32_t bf[8][2];
#pragma unroll
            for (int p = 0; p < 4; p++)
                ldsm4(bf[2 * p][0], bf[2 * p][1], bf[2 * p + 1][0], bf[2 * p + 1][1],
                      ks_b + (uint32_t)((p * 16 + b_r) * 72 + kb + b_c) * 2u);
#pragma unroll
            for (int nt = 0; nt < 8; nt++)
                mma_f16(sacc[nt][0], sacc[nt][1], sacc[nt][2], sacc[nt][3],
                        qa[ks][0], qa[ks][1], qa[ks][2], qa[ks][3],
                        bf[nt][0], bf[nt][1]);
        }

        if (kt >= 2 * qt) {
            const int sb = kt * 64;
#pragma unroll
            for (int nt = 0; nt < 8; nt++) {
                const int c0 = sb + nt * 8 + 2 * t, c1 = c0 + 1;
                if (c0 > r0) sacc[nt][0] = -1e30f;
                if (c1 > r0) sacc[nt][1] = -1e30f;
                if (c0 > r1) sacc[nt][2] = -1e30f;
                if (c1 > r1) sacc[nt][3] = -1e30f;
            }
        }

        float mx0 = -1e30f, mx1 = -1e30f;
#pragma unroll
        for (int nt = 0; nt < 8; nt++) {
            mx0 = fmaxf(mx0, fmaxf(sacc[nt][0], sacc[nt][1]));
            mx1 = fmaxf(mx1, fmaxf(sacc[nt][2], sacc[nt][3]));
        }
        mx0 = fmaxf(mx0, __shfl_xor_sync(0xffffffffu, mx0, 1));
        mx0 = fmaxf(mx0, __shfl_xor_sync(0xffffffffu, mx0, 2));
        mx1 = fmaxf(mx1, __shfl_xor_sync(0xffffffffu, mx1, 1));
        mx1 = fmaxf(mx1, __shfl_xor_sync(0xffffffffu, mx1, 2));

        const float mn0 = fmaxf(m0, mx0), mn1 = fmaxf(m1, mx1);
        const float f0 = ex2(m0 - mn0), f1 = ex2(m1 - mn1);
        float ls0 = 0.f, ls1 = 0.f;
#pragma unroll
        for (int nt = 0; nt < 8; nt++) {
            const float p00 = ex2(sacc[nt][0] - mn0);
            const float p01 = ex2(sacc[nt][1] - mn0);
            const float p10 = ex2(sacc[nt][2] - mn1);
            const float p11 = ex2(sacc[nt][3] - mn1);
            ls0 += p00 + p01;
            ls1 += p10 + p11;
            *(uint32_t*)&Ps[(mb + g) * 72 + nt * 8 + 2 * t]     = pack_h2(p00, p01);
            *(uint32_t*)&Ps[(mb + g + 8) * 72 + nt * 8 + 2 * t] = pack_h2(p10, p11);
        }
        ls0 += __shfl_xor_sync(0xffffffffu, ls0, 1);
        ls0 += __shfl_xor_sync(0xffffffffu, ls0, 2);
        ls1 += __shfl_xor_sync(0xffffffffu, ls1, 1);
        ls1 += __shfl_xor_sync(0xffffffffu, ls1, 2);
        l0 = l0 * f0 + ls0;
        l1 = l1 * f1 + ls1;
        m0 = mn0; m1 = mn1;
#pragma unroll
        for (int nt = 0; nt < 8; nt++) {
            oacc[nt][0] *= f0; oacc[nt][1] *= f0;
            oacc[nt][2] *= f1; oacc[nt][3] *= f1;
        }
        __syncwarp();   // P rows are private to this warp

        // O += P @ V   (V^T tile: rows d, cols s)
#pragma unroll
        for (int ks = 0; ks < 4; ks++) {
            const int kb = ks * 16;
            uint32_t pa[4];
            ldsm4(pa[0], pa[1], pa[2], pa[3],
                  pmb + (uint32_t)((mb + a_r) * 72 + kb + a_c) * 2u);
            uint32_t bf[8][2];
#pragma unroll
            for (int p = 0; p < 4; p++)
                ldsm4(bf[2 * p][0], bf[2 * p][1], bf[2 * p + 1][0], bf[2 * p + 1][1],
                      vs_b + (uint32_t)((p * 16 + b_r) * 72 + kb + b_c) * 2u);
#pragma unroll
            for (int nt = 0; nt < 8; nt++)
                mma_f16(oacc[nt][0], oacc[nt][1], oacc[nt][2], oacc[nt][3],
                        pa[0], pa[1], pa[2], pa[3], bf[nt][0], bf[nt][1]);
        }
    }

    // epilogue -> g_att half [b][t][h][d]
    const float i0 = 1.0f / l0, i1 = 1.0f / l1;
    __half* O0 = (__half*)g_att + ((size_t)(b * TT + r0) * NH + h) * HD;
    __half* O1 = (__half*)g_att + ((size_t)(b * TT + r1) * NH + h) * HD;
#pragma unroll
    for (int nt = 0; nt < 8; nt++) {
        const int d = nt * 8 + 2 * t;
        *(uint32_t*)&O0[d] = pack_h2(oacc[nt][0] * i0, oacc[nt][1] * i0);
        *(uint32_t*)&O1[d] = pack_h2(oacc[nt][2] * i1, oacc[nt][3] * i1);
    }
}

// ---------------------------------------------------------------------------
// kernel_launch
// ---------------------------------------------------------------------------
extern "C" void kernel_launch(void* const* d_in, const int* in_sizes, int n_in,
                              void* d_out, int out_size)
{
    const float* x      = (const float*)d_in[0];
    const float* w_qkv  = (const float*)d_in[1];
    const float* b_qkv  = (const float*)d_in[2];
    const float* w_proj = (const float*)d_in[3];
    const float* b_proj = (const float*)d_in[4];
    float* out = (float*)d_out;

    const int M = BB * TT;  // 4096

    cudaFuncSetAttribute(mma_gemm<0>, cudaFuncAttributeMaxDynamicSharedMemorySize, GSMEM_BYTES);
    cudaFuncSetAttribute(mma_gemm<1>, cudaFuncAttributeMaxDynamicSharedMemorySize, GSMEM_BYTES);
    cudaFuncSetAttribute(flash_mma, cudaFuncAttributeMaxDynamicSharedMemorySize, FLASH_SMEM);

    // 0) prepass: round x; transpose+round weights to [N][K] half
    round_x_k<<<512, 256>>>(x);
    transpose_w<0><<<dim3(3 * DM / 32, DM / 32), dim3(32, 8)>>>(w_qkv, DM, 3 * DM);
    transpose_w<1><<<dim3(DM / 32, DM / 32), dim3(32, 8)>>>(w_proj, DM, DM);

    // 1) QKV projection (fp16 m16n8k16, ldmatrix, BK=64, 3-stage cp.async)
    mma_gemm<0><<<dim3(3 * DM / 128, M / 128), 256, GSMEM_BYTES>>>(b_qkv, nullptr, M, 3 * DM, DM);

    // 2) causal flash attention (fp16 MMA + ldmatrix, fp32 softmax) -> g_att
    flash_mma<<<dim3(TT / 128, NH, BB), 256, FLASH_SMEM>>>();

    // 3) output projection -> out (fp32)
    mma_gemm<1><<<dim3(DM / 128, M / 128), 256, GSMEM_BYTES>>>(b_proj, out, M, DM, DM);
}